// round 13
// baseline (speedup 1.0000x reference)
#include <cuda_runtime.h>
#include <cuda_fp16.h>
#include <cstdint>
#include <math.h>

// ---------------------------------------------------------------------------
// SimpleTransformerBlock via warp-level fp16 mma.sync (sm_103 non-'a' PTX
// target: no tcgen05). R13: R10 GEMM config (best known: 128x128 CTA, 32x64
// warp tile, 16 warps/SM) made PERSISTENT (296 CTAs grid-striding tiles) to
// eliminate wave-quantization tails (proj/MLP2 lose 13.5% to 3.46-wave grids).
// ---------------------------------------------------------------------------

#define M_ROWS 16384
#define PERSIST_CTAS 296      // 148 SMs x 2 CTAs/SM

// fp32 scratch
__device__ float g_x1  [(size_t)M_ROWS * 1024];
// fp16 scratch
__device__ __half g_qkvh [(size_t)M_ROWS * 3072];
__device__ __half g_act  [(size_t)M_ROWS * 1024];
__device__ __half g_amlp [(size_t)M_ROWS * 4096];
__device__ __half g_ws_qkv [(size_t)3072 * 1024];
__device__ __half g_ws_proj[(size_t)1024 * 1024];
__device__ __half g_ws_w1  [(size_t)4096 * 1024];
__device__ __half g_ws_w2  [(size_t)1024 * 4096];

// ---------------------------------------------------------------------------
// PTX wrappers
// ---------------------------------------------------------------------------
__device__ __forceinline__ uint32_t smem_u32(const void* p) {
    uint32_t a;
    asm("{ .reg .u64 t; cvta.to.shared.u64 t, %1; cvt.u32.u64 %0, t; }" : "=r"(a) : "l"(p));
    return a;
}
__device__ __forceinline__ void cp_async16(uint32_t dst, const void* src) {
    asm volatile("cp.async.cg.shared.global [%0], [%1], 16;" :: "r"(dst), "l"(src));
}
__device__ __forceinline__ void cp_commit() {
    asm volatile("cp.async.commit_group;" ::: "memory");
}
__device__ __forceinline__ void cp_wait1() {
    asm volatile("cp.async.wait_group 1;" ::: "memory");
}
__device__ __forceinline__ void ldsm_x4(uint32_t* r, uint32_t addr) {
    asm volatile("ldmatrix.sync.aligned.m8n8.x4.shared.b16 {%0,%1,%2,%3}, [%4];"
                 : "=r"(r[0]), "=r"(r[1]), "=r"(r[2]), "=r"(r[3]) : "r"(addr));
}
__device__ __forceinline__ void mma16816(float* c, const uint32_t* a, uint32_t b0, uint32_t b1) {
    asm("mma.sync.aligned.m16n8k16.row.col.f32.f16.f16.f32 "
        "{%0,%1,%2,%3}, {%4,%5,%6,%7}, {%8,%9}, {%0,%1,%2,%3};"
        : "+f"(c[0]), "+f"(c[1]), "+f"(c[2]), "+f"(c[3])
        : "r"(a[0]), "r"(a[1]), "r"(a[2]), "r"(a[3]), "r"(b0), "r"(b1));
}
__device__ __forceinline__ uint32_t pack_h2(float x, float y) {
    __half2 h = __floats2half2_rn(x, y);
    return *(uint32_t*)&h;
}

// ---------------------------------------------------------------------------
// LayerNorm -> fp16 store (row width 1024)
// ---------------------------------------------------------------------------
__global__ __launch_bounds__(256) void ln_h_kernel(
    const float* __restrict__ x, const float* __restrict__ w,
    const float* __restrict__ b, __half* __restrict__ out)
{
    const int row = blockIdx.x;
    const int t   = threadIdx.x;
    const float4 v = ((const float4*)(x + (size_t)row * 1024))[t];
    float s  = v.x + v.y + v.z + v.w;
    float sq = v.x*v.x + v.y*v.y + v.z*v.z + v.w*v.w;
    #pragma unroll
    for (int o = 16; o > 0; o >>= 1) {
        s  += __shfl_xor_sync(0xffffffffu, s,  o);
        sq += __shfl_xor_sync(0xffffffffu, sq, o);
    }
    __shared__ float sm[8], sm2[8];
    const int warp = t >> 5, lane = t & 31;
    if (lane == 0) { sm[warp] = s; sm2[warp] = sq; }
    __syncthreads();
    if (t == 0) {
        float a = 0.f, c = 0.f;
        #pragma unroll
        for (int i = 0; i < 8; i++) { a += sm[i]; c += sm2[i]; }
        sm[0] = a; sm2[0] = c;
    }
    __syncthreads();
    const float mean = sm[0]  * (1.f / 1024.f);
    const float var  = sm2[0] * (1.f / 1024.f) - mean * mean;
    const float inv  = rsqrtf(var + 1e-5f);
    const float4 wv = ((const float4*)w)[t];
    const float4 bv = ((const float4*)b)[t];
    uint2 H;
    H.x = pack_h2((v.x - mean) * inv * wv.x + bv.x, (v.y - mean) * inv * wv.y + bv.y);
    H.y = pack_h2((v.z - mean) * inv * wv.z + bv.z, (v.w - mean) * inv * wv.w + bv.w);
    *(uint2*)(out + (size_t)row * 1024 + t * 4) = H;
}

// ---------------------------------------------------------------------------
// fp32 -> fp16 convert (weights)
// ---------------------------------------------------------------------------
__global__ __launch_bounds__(256) void conv_w_kernel(
    const float* __restrict__ in, __half* __restrict__ out)
{
    const size_t e = ((size_t)blockIdx.x * 256 + threadIdx.x) * 4;
    const float4 v = *(const float4*)(in + e);
    uint2 H;
    H.x = pack_h2(v.x, v.y);
    H.y = pack_h2(v.z, v.w);
    *(uint2*)(out + e) = H;
}

// ---------------------------------------------------------------------------
// Per-position head-mix attention, fp16 in/out, padded rows (no conflicts).
// ---------------------------------------------------------------------------
#define ATT_PAD 68
__global__ __launch_bounds__(128) void attn_h_kernel(
    const __half* __restrict__ qkv, __half* __restrict__ out)
{
    const int pos = blockIdx.x;
    const int t   = threadIdx.x;
    const __half* base = qkv + (size_t)pos * 3072;

    __shared__ __half sQ[16 * ATT_PAD], sK[16 * ATT_PAD], sV[16 * ATT_PAD];
    __shared__ float S[16][17];

    #pragma unroll
    for (int i = 0; i < 6; i++) {
        const int chunk = t + i * 128;
        const int idx   = chunk * 4;
        const uint2 d   = *(const uint2*)(base + idx);
        const int sec   = idx >> 10;
        const int rem   = idx & 1023;
        const int r     = rem >> 6;
        const int c     = rem & 63;
        __half* dst = (sec == 0 ? sQ : (sec == 1 ? sK : sV)) + r * ATT_PAD + c;
        *(uint2*)dst = d;
    }
    __syncthreads();

    #pragma unroll
    for (int ee = 0; ee < 2; ee++) {
        const int e = t + ee * 128;
        const int h = e >> 4, g = e & 15;
        const __half2* qh = (const __half2*)(sQ + h * ATT_PAD);
        const __half2* kh = (const __half2*)(sK + g * ATT_PAD);
        float acc = 0.f;
        #pragma unroll
        for (int d2 = 0; d2 < 32; d2++) {
            const float2 a = __half22float2(qh[d2]);
            const float2 b = __half22float2(kh[d2]);
            acc = fmaf(a.x, b.x, acc);
            acc = fmaf(a.y, b.y, acc);
        }
        S[h][g] = acc * 0.125f;
    }
    __syncthreads();

    if (t < 16) {
        float m = -1e30f;
        #pragma unroll
        for (int g = 0; g < 16; g++) m = fmaxf(m, S[t][g]);
        float sum = 0.f;
        #pragma unroll
        for (int g = 0; g < 16; g++) { float e = expf(S[t][g] - m); S[t][g] = e; sum += e; }
        const float inv = 1.f / sum;
        #pragma unroll
        for (int g = 0; g < 16; g++) S[t][g] *= inv;
    }
    __syncthreads();

    const int h = t >> 3;
    const int d = (t & 7) * 8;
    float r[8];
    #pragma unroll
    for (int j = 0; j < 8; j++) r[j] = 0.f;
    #pragma unroll
    for (int g = 0; g < 16; g++) {
        const float p = S[h][g];
        const __half2* vh = (const __half2*)(sV + g * ATT_PAD + d);
        #pragma unroll
        for (int j = 0; j < 4; j++) {
            const float2 f = __half22float2(vh[j]);
            r[2 * j]     = fmaf(p, f.x, r[2 * j]);
            r[2 * j + 1] = fmaf(p, f.y, r[2 * j + 1]);
        }
    }
    uint4 o;
    o.x = pack_h2(r[0], r[1]);
    o.y = pack_h2(r[2], r[3]);
    o.z = pack_h2(r[4], r[5]);
    o.w = pack_h2(r[6], r[7]);
    *(uint4*)(out + (size_t)pos * 1024 + t * 8) = o;
}

// ---------------------------------------------------------------------------
// Persistent fp16 mma.sync GEMM: 296 CTAs grid-stride over 128x128 tiles.
// Per tile: 3-stage cp.async pipeline, 8 warps 4x2 (32x64 warp tiles).
// Swizzle identity: swz(r*128+c*16) = r*128 + (c*16 ^ ((r&7)<<4)).
// ---------------------------------------------------------------------------
#define STAGES 3
#define STAGE_BYTES 32768

#define EPI_BIAS 0
#define EPI_RES  1
#define EPI_GELU 2

__device__ __forceinline__ float gelu_exact(float v) {
    return 0.5f * v * (1.0f + erff(v * 0.70710678118654752f));
}

template<int EPI, bool H_OUT, int N, int KK>
__global__ __launch_bounds__(256, 2) void gemm_mma(
    const __half* __restrict__ A,   // [M_ROWS, KK]
    const __half* __restrict__ B,   // [N, KK]
    const float* __restrict__ bias,
    const float* __restrict__ res,
    float* __restrict__ C,
    __half* __restrict__ Ch)        // fp16 out, stride N
{
    extern __shared__ char smem[];
    const uint32_t sbase = smem_u32(smem);

    const int tid  = threadIdx.x;
    const int wid  = tid >> 5;
    const int lane = tid & 31;
    const int wm   = wid & 3;
    const int wn   = wid >> 2;

    // ---- per-thread invariants (tile-independent) --------------------------
    const int l_c8   = (tid & 7) << 3;
    const int l_row0 = tid >> 3;
    const uint32_t s_sw = (uint32_t)((l_c8 * 2) ^ ((l_row0 & 7) << 4));

    const uint32_t lh16 = (uint32_t)(lane >> 4) << 4;
    uint32_t Ra[2], Rb[4];
    #pragma unroll
    for (int mt = 0; mt < 2; mt++) {
        const int r = wm * 32 + mt * 16 + (lane & 15);
        Ra[mt] = (uint32_t)(r * 128) + ((((uint32_t)r & 7) << 4) ^ lh16);
    }
    #pragma unroll
    for (int bt = 0; bt < 4; bt++) {
        const int r = wn * 64 + bt * 16 + (lane & 15);
        Rb[bt] = 16384u + (uint32_t)(r * 128) + ((((uint32_t)r & 7) << 4) ^ lh16);
    }

    constexpr int NT_N = N / 128;
    constexpr int NT   = (M_ROWS / 128) * NT_N;
    constexpr int S    = KK >> 6;

    for (int tile = blockIdx.x; tile < NT; tile += PERSIST_CTAS) {
        const int bm = (tile / NT_N) * 128;
        const int bn = (tile % NT_N) * 128;

        const __half* Ag = A + (size_t)(bm + l_row0) * KK + l_c8;
        const __half* Bg = B + (size_t)(bn + l_row0) * KK + l_c8;

        float acc[2][8][4];
        #pragma unroll
        for (int i = 0; i < 2; i++)
            #pragma unroll
            for (int j = 0; j < 8; j++)
                #pragma unroll
                for (int k = 0; k < 4; k++) acc[i][j][k] = 0.f;

        auto load_stage = [&](int k0, uint32_t sstage) {
            #pragma unroll
            for (int i = 0; i < 4; i++) {
                const uint32_t so = (uint32_t)((l_row0 + 32 * i) * 128) + s_sw;
                cp_async16(sstage + so,          Ag + (size_t)(32 * i) * KK + k0);
                cp_async16(sstage + 16384u + so, Bg + (size_t)(32 * i) * KK + k0);
            }
        };

        // guard: previous tile's last compute stage used buffer 0; make sure
        // all warps left it before the new prologue overwrites stages 0/1.
        __syncthreads();

        load_stage(0,  sbase);               cp_commit();
        load_stage(64, sbase + STAGE_BYTES); cp_commit();

        uint32_t s_cur  = sbase;
        uint32_t s_next = sbase + 2 * STAGE_BYTES;
        #pragma unroll 1
        for (int s = 0; s < S; s++) {
            cp_wait1();
            __syncthreads();

            if (s + 2 < S) load_stage((s + 2) << 6, s_next);
            cp_commit();
            s_next += STAGE_BYTES;
            if (s_next == sbase + 3 * STAGE_BYTES) s_next = sbase;

            #pragma unroll
            for (int ks = 0; ks < 4; ks++) {
                const uint32_t kx = (uint32_t)(ks * 32);
                uint32_t a[2][4];
                #pragma unroll
                for (int mt = 0; mt < 2; mt++)
                    ldsm_x4(a[mt], (s_cur + Ra[mt]) ^ kx);
                uint32_t bfr[4][4];
                #pragma unroll
                for (int bt = 0; bt < 4; bt++)
                    ldsm_x4(bfr[bt], (s_cur + Rb[bt]) ^ kx);
                #pragma unroll
                for (int mt = 0; mt < 2; mt++)
                    #pragma unroll
                    for (int nt = 0; nt < 8; nt++) {
                        const int bt = nt >> 1, wh = nt & 1;
                        mma16816(acc[mt][nt], a[mt], bfr[bt][wh], bfr[bt][wh + 2]);
                    }
            }
            s_cur += STAGE_BYTES;
            if (s_cur == sbase + 3 * STAGE_BYTES) s_cur = sbase;
        }

        // epilogue (registers + global only; no smem)
        const int colq = (lane & 3) * 2;
        const int rowq = lane >> 2;
        #pragma unroll
        for (int mt = 0; mt < 2; mt++) {
            #pragma unroll
            for (int nt = 0; nt < 8; nt++) {
                const int col = bn + wn * 64 + nt * 8 + colq;
                const float2 bz = *(const float2*)(bias + col);
                #pragma unroll
                for (int hh = 0; hh < 2; hh++) {
                    const int grow = bm + wm * 32 + mt * 16 + rowq + hh * 8;
                    float2 v;
                    v.x = acc[mt][nt][hh * 2 + 0] + bz.x;
                    v.y = acc[mt][nt][hh * 2 + 1] + bz.y;
                    if (EPI == EPI_RES) {
                        const float2 r = *(const float2*)(res + (size_t)grow * N + col);
                        v.x += r.x; v.y += r.y;
                    }
                    if (EPI == EPI_GELU) {
                        v.x = gelu_exact(v.x); v.y = gelu_exact(v.y);
                    }
                    if (H_OUT) {
                        *(uint32_t*)(Ch + (size_t)grow * N + col) = pack_h2(v.x, v.y);
                    } else {
                        *(float2*)(C + (size_t)grow * N + col) = v;
                    }
                }
            }
        }
    }
}

// ---------------------------------------------------------------------------
// Launch
// ---------------------------------------------------------------------------
extern "C" void kernel_launch(void* const* d_in, const int* in_sizes, int n_in,
                              void* d_out, int out_size)
{
    const float* x      = (const float*)d_in[0];
    const float* qkv_w  = (const float*)d_in[1];
    const float* qkv_b  = (const float*)d_in[2];
    const float* proj_w = (const float*)d_in[3];
    const float* proj_b = (const float*)d_in[4];
    const float* ln1_w  = (const float*)d_in[5];
    const float* ln1_b  = (const float*)d_in[6];
    const float* ln2_w  = (const float*)d_in[7];
    const float* ln2_b  = (const float*)d_in[8];
    const float* mlp_w1 = (const float*)d_in[9];
    const float* mlp_b1 = (const float*)d_in[10];
    const float* mlp_w2 = (const float*)d_in[11];
    const float* mlp_b2 = (const float*)d_in[12];
    float* out = (float*)d_out;

    float *x1;
    __half *qkvh, *act, *amlp, *wsq, *wsp, *ws1, *ws2;
    cudaGetSymbolAddress((void**)&x1,   g_x1);
    cudaGetSymbolAddress((void**)&qkvh, g_qkvh);
    cudaGetSymbolAddress((void**)&act,  g_act);
    cudaGetSymbolAddress((void**)&amlp, g_amlp);
    cudaGetSymbolAddress((void**)&wsq,  g_ws_qkv);
    cudaGetSymbolAddress((void**)&wsp,  g_ws_proj);
    cudaGetSymbolAddress((void**)&ws1,  g_ws_w1);
    cudaGetSymbolAddress((void**)&ws2,  g_ws_w2);

    const int SMEM = STAGES * STAGE_BYTES;   // 96KB
    cudaFuncSetAttribute((gemm_mma<EPI_BIAS, true,  3072, 1024>), cudaFuncAttributeMaxDynamicSharedMemorySize, SMEM);
    cudaFuncSetAttribute((gemm_mma<EPI_RES,  false, 1024, 1024>), cudaFuncAttributeMaxDynamicSharedMemorySize, SMEM);
    cudaFuncSetAttribute((gemm_mma<EPI_GELU, true,  4096, 1024>), cudaFuncAttributeMaxDynamicSharedMemorySize, SMEM);
    cudaFuncSetAttribute((gemm_mma<EPI_RES,  false, 1024, 4096>), cudaFuncAttributeMaxDynamicSharedMemorySize, SMEM);

    const int M = M_ROWS;

    conv_w_kernel<<<3072 * 1024 / 1024, 256>>>(qkv_w, wsq);
    ln_h_kernel<<<M, 256>>>(x, ln1_w, ln1_b, act);
    conv_w_kernel<<<1024 * 1024 / 1024, 256>>>(proj_w, wsp);

    // launch slot 3: profiled
    gemm_mma<EPI_BIAS, true, 3072, 1024><<<PERSIST_CTAS, 256, SMEM>>>(
        act, wsq, qkv_b, nullptr, nullptr, qkvh);

    attn_h_kernel<<<M, 128>>>(qkvh, act);

    gemm_mma<EPI_RES, false, 1024, 1024><<<PERSIST_CTAS, 256, SMEM>>>(
        act, wsp, proj_b, x, x1, nullptr);

    ln_h_kernel<<<M, 256>>>(x1, ln2_w, ln2_b, act);
    conv_w_kernel<<<4096 * 1024 / 1024, 256>>>(mlp_w1, ws1);

    gemm_mma<EPI_GELU, true, 4096, 1024><<<PERSIST_CTAS, 256, SMEM>>>(
        act, ws1, mlp_b1, nullptr, nullptr, amlp);

    conv_w_kernel<<<1024 * 4096 / 1024, 256>>>(mlp_w2, ws2);

    gemm_mma<EPI_RES, false, 1024, 4096><<<PERSIST_CTAS, 256, SMEM>>>(
        amlp, ws2, mlp_b2, x1, out, nullptr);
}

// round 14
// speedup vs baseline: 1.0447x; 1.0447x over previous
#include <cuda_runtime.h>
#include <cuda_fp16.h>
#include <cstdint>
#include <math.h>

// ---------------------------------------------------------------------------
// SimpleTransformerBlock via warp-level fp16 mma.sync (sm_103 non-'a' PTX
// target: no tcgen05). R14: exact R10 GEMM config (best known: 128x128 CTA,
// 32x64 warp tile, 16 warps/SM, 3-stage cp.async) + all 4 weight conversions
// merged into ONE launch (kills 3 launch gaps + small-grid tails).
// ---------------------------------------------------------------------------

#define M_ROWS 16384

// fp32 scratch
__device__ float g_x1  [(size_t)M_ROWS * 1024];
// fp16 scratch
__device__ __half g_qkvh [(size_t)M_ROWS * 3072];
__device__ __half g_act  [(size_t)M_ROWS * 1024];
__device__ __half g_amlp [(size_t)M_ROWS * 4096];
__device__ __half g_ws_qkv [(size_t)3072 * 1024];
__device__ __half g_ws_proj[(size_t)1024 * 1024];
__device__ __half g_ws_w1  [(size_t)4096 * 1024];
__device__ __half g_ws_w2  [(size_t)1024 * 4096];

// ---------------------------------------------------------------------------
// PTX wrappers
// ---------------------------------------------------------------------------
__device__ __forceinline__ uint32_t smem_u32(const void* p) {
    uint32_t a;
    asm("{ .reg .u64 t; cvta.to.shared.u64 t, %1; cvt.u32.u64 %0, t; }" : "=r"(a) : "l"(p));
    return a;
}
__device__ __forceinline__ void cp_async16(uint32_t dst, const void* src) {
    asm volatile("cp.async.cg.shared.global [%0], [%1], 16;" :: "r"(dst), "l"(src));
}
__device__ __forceinline__ void cp_commit() {
    asm volatile("cp.async.commit_group;" ::: "memory");
}
__device__ __forceinline__ void cp_wait1() {
    asm volatile("cp.async.wait_group 1;" ::: "memory");
}
__device__ __forceinline__ void ldsm_x4(uint32_t* r, uint32_t addr) {
    asm volatile("ldmatrix.sync.aligned.m8n8.x4.shared.b16 {%0,%1,%2,%3}, [%4];"
                 : "=r"(r[0]), "=r"(r[1]), "=r"(r[2]), "=r"(r[3]) : "r"(addr));
}
__device__ __forceinline__ void mma16816(float* c, const uint32_t* a, uint32_t b0, uint32_t b1) {
    asm("mma.sync.aligned.m16n8k16.row.col.f32.f16.f16.f32 "
        "{%0,%1,%2,%3}, {%4,%5,%6,%7}, {%8,%9}, {%0,%1,%2,%3};"
        : "+f"(c[0]), "+f"(c[1]), "+f"(c[2]), "+f"(c[3])
        : "r"(a[0]), "r"(a[1]), "r"(a[2]), "r"(a[3]), "r"(b0), "r"(b1));
}
__device__ __forceinline__ uint32_t pack_h2(float x, float y) {
    __half2 h = __floats2half2_rn(x, y);
    return *(uint32_t*)&h;
}

// ---------------------------------------------------------------------------
// LayerNorm -> fp16 store (row width 1024)
// ---------------------------------------------------------------------------
__global__ __launch_bounds__(256) void ln_h_kernel(
    const float* __restrict__ x, const float* __restrict__ w,
    const float* __restrict__ b, __half* __restrict__ out)
{
    const int row = blockIdx.x;
    const int t   = threadIdx.x;
    const float4 v = ((const float4*)(x + (size_t)row * 1024))[t];
    float s  = v.x + v.y + v.z + v.w;
    float sq = v.x*v.x + v.y*v.y + v.z*v.z + v.w*v.w;
    #pragma unroll
    for (int o = 16; o > 0; o >>= 1) {
        s  += __shfl_xor_sync(0xffffffffu, s,  o);
        sq += __shfl_xor_sync(0xffffffffu, sq, o);
    }
    __shared__ float sm[8], sm2[8];
    const int warp = t >> 5, lane = t & 31;
    if (lane == 0) { sm[warp] = s; sm2[warp] = sq; }
    __syncthreads();
    if (t == 0) {
        float a = 0.f, c = 0.f;
        #pragma unroll
        for (int i = 0; i < 8; i++) { a += sm[i]; c += sm2[i]; }
        sm[0] = a; sm2[0] = c;
    }
    __syncthreads();
    const float mean = sm[0]  * (1.f / 1024.f);
    const float var  = sm2[0] * (1.f / 1024.f) - mean * mean;
    const float inv  = rsqrtf(var + 1e-5f);
    const float4 wv = ((const float4*)w)[t];
    const float4 bv = ((const float4*)b)[t];
    uint2 H;
    H.x = pack_h2((v.x - mean) * inv * wv.x + bv.x, (v.y - mean) * inv * wv.y + bv.y);
    H.y = pack_h2((v.z - mean) * inv * wv.z + bv.z, (v.w - mean) * inv * wv.w + bv.w);
    *(uint2*)(out + (size_t)row * 1024 + t * 4) = H;
}

// ---------------------------------------------------------------------------
// ALL weight fp32->fp16 conversions in one launch.
// Block ranges (1024 floats per block):
//   [0, 3072)        qkv_w  -> ws_qkv
//   [3072, 4096)     proj_w -> ws_proj
//   [4096, 8192)     mlp_w1 -> ws_w1
//   [8192, 12288)    mlp_w2 -> ws_w2
// ---------------------------------------------------------------------------
__global__ __launch_bounds__(256) void conv_all_kernel(
    const float* __restrict__ qkv_w,  __half* __restrict__ o_qkv,
    const float* __restrict__ proj_w, __half* __restrict__ o_proj,
    const float* __restrict__ w1,     __half* __restrict__ o_w1,
    const float* __restrict__ w2,     __half* __restrict__ o_w2)
{
    const int blk = blockIdx.x;
    const float* src;
    __half* dst;
    size_t base;
    if (blk < 3072)      { src = qkv_w;  dst = o_qkv;  base = (size_t)blk * 1024; }
    else if (blk < 4096) { src = proj_w; dst = o_proj; base = (size_t)(blk - 3072) * 1024; }
    else if (blk < 8192) { src = w1;     dst = o_w1;   base = (size_t)(blk - 4096) * 1024; }
    else                 { src = w2;     dst = o_w2;   base = (size_t)(blk - 8192) * 1024; }

    const size_t e = base + (size_t)threadIdx.x * 4;
    const float4 v = *(const float4*)(src + e);
    uint2 H;
    H.x = pack_h2(v.x, v.y);
    H.y = pack_h2(v.z, v.w);
    *(uint2*)(dst + e) = H;
}

// ---------------------------------------------------------------------------
// Per-position head-mix attention, fp16 in/out, padded rows (no conflicts).
// ---------------------------------------------------------------------------
#define ATT_PAD 68
__global__ __launch_bounds__(128) void attn_h_kernel(
    const __half* __restrict__ qkv, __half* __restrict__ out)
{
    const int pos = blockIdx.x;
    const int t   = threadIdx.x;
    const __half* base = qkv + (size_t)pos * 3072;

    __shared__ __half sQ[16 * ATT_PAD], sK[16 * ATT_PAD], sV[16 * ATT_PAD];
    __shared__ float S[16][17];

    #pragma unroll
    for (int i = 0; i < 6; i++) {
        const int chunk = t + i * 128;
        const int idx   = chunk * 4;
        const uint2 d   = *(const uint2*)(base + idx);
        const int sec   = idx >> 10;
        const int rem   = idx & 1023;
        const int r     = rem >> 6;
        const int c     = rem & 63;
        __half* dst = (sec == 0 ? sQ : (sec == 1 ? sK : sV)) + r * ATT_PAD + c;
        *(uint2*)dst = d;
    }
    __syncthreads();

    #pragma unroll
    for (int ee = 0; ee < 2; ee++) {
        const int e = t + ee * 128;
        const int h = e >> 4, g = e & 15;
        const __half2* qh = (const __half2*)(sQ + h * ATT_PAD);
        const __half2* kh = (const __half2*)(sK + g * ATT_PAD);
        float acc = 0.f;
        #pragma unroll
        for (int d2 = 0; d2 < 32; d2++) {
            const float2 a = __half22float2(qh[d2]);
            const float2 b = __half22float2(kh[d2]);
            acc = fmaf(a.x, b.x, acc);
            acc = fmaf(a.y, b.y, acc);
        }
        S[h][g] = acc * 0.125f;
    }
    __syncthreads();

    if (t < 16) {
        float m = -1e30f;
        #pragma unroll
        for (int g = 0; g < 16; g++) m = fmaxf(m, S[t][g]);
        float sum = 0.f;
        #pragma unroll
        for (int g = 0; g < 16; g++) { float e = expf(S[t][g] - m); S[t][g] = e; sum += e; }
        const float inv = 1.f / sum;
        #pragma unroll
        for (int g = 0; g < 16; g++) S[t][g] *= inv;
    }
    __syncthreads();

    const int h = t >> 3;
    const int d = (t & 7) * 8;
    float r[8];
    #pragma unroll
    for (int j = 0; j < 8; j++) r[j] = 0.f;
    #pragma unroll
    for (int g = 0; g < 16; g++) {
        const float p = S[h][g];
        const __half2* vh = (const __half2*)(sV + g * ATT_PAD + d);
        #pragma unroll
        for (int j = 0; j < 4; j++) {
            const float2 f = __half22float2(vh[j]);
            r[2 * j]     = fmaf(p, f.x, r[2 * j]);
            r[2 * j + 1] = fmaf(p, f.y, r[2 * j + 1]);
        }
    }
    uint4 o;
    o.x = pack_h2(r[0], r[1]);
    o.y = pack_h2(r[2], r[3]);
    o.z = pack_h2(r[4], r[5]);
    o.w = pack_h2(r[6], r[7]);
    *(uint4*)(out + (size_t)pos * 1024 + t * 8) = o;
}

// ---------------------------------------------------------------------------
// fp16 mma.sync GEMM (R10 exact): C = A[M,KK] @ B[N,KK]^T + bias
// (+res | +gelu; fp32 or fp16 out). BM=BN=128, BK=64, 256 thr (8 warps 4x2,
// warp tile 32x64), 3-stage cp.async, 2 CTAs/SM.
// Swizzle identity: swz(r*128+c*16) = r*128 + (c*16 ^ ((r&7)<<4)).
// ---------------------------------------------------------------------------
#define STAGES 3
#define STAGE_BYTES 32768

#define EPI_BIAS 0
#define EPI_RES  1
#define EPI_GELU 2

__device__ __forceinline__ float gelu_exact(float v) {
    return 0.5f * v * (1.0f + erff(v * 0.70710678118654752f));
}

template<int EPI, bool H_OUT, int N, int KK>
__global__ __launch_bounds__(256, 2) void gemm_mma(
    const __half* __restrict__ A,   // [M, KK]
    const __half* __restrict__ B,   // [N, KK]
    const float* __restrict__ bias,
    const float* __restrict__ res,
    float* __restrict__ C,
    __half* __restrict__ Ch)        // fp16 out, stride N
{
    extern __shared__ char smem[];
    const uint32_t sbase = smem_u32(smem);

    const int tid  = threadIdx.x;
    const int wid  = tid >> 5;
    const int lane = tid & 31;
    const int wm   = wid & 3;
    const int wn   = wid >> 2;

    const int bm = blockIdx.y * 128;
    const int bn = blockIdx.x * 128;

    // ---- loader invariants: 4 chunks/operand/stage, 16B each -------------
    const int l_c8   = (tid & 7) << 3;
    const int l_row0 = tid >> 3;
    const __half* Ag = A + (size_t)(bm + l_row0) * KK + l_c8;
    const __half* Bg = B + (size_t)(bn + l_row0) * KK + l_c8;
    const uint32_t s_sw = (uint32_t)((l_c8 * 2) ^ ((l_row0 & 7) << 4));

    // ---- ldsm invariants --------------------------------------------------
    const uint32_t lh16 = (uint32_t)(lane >> 4) << 4;
    uint32_t Ra[2], Rb[4];
    #pragma unroll
    for (int mt = 0; mt < 2; mt++) {
        const int r = wm * 32 + mt * 16 + (lane & 15);
        Ra[mt] = (uint32_t)(r * 128) + ((((uint32_t)r & 7) << 4) ^ lh16);
    }
    #pragma unroll
    for (int bt = 0; bt < 4; bt++) {
        const int r = wn * 64 + bt * 16 + (lane & 15);
        Rb[bt] = 16384u + (uint32_t)(r * 128) + ((((uint32_t)r & 7) << 4) ^ lh16);
    }

    float acc[2][8][4];
    #pragma unroll
    for (int i = 0; i < 2; i++)
        #pragma unroll
        for (int j = 0; j < 8; j++)
            #pragma unroll
            for (int k = 0; k < 4; k++) acc[i][j][k] = 0.f;

    auto load_stage = [&](int k0, uint32_t sstage) {
        #pragma unroll
        for (int i = 0; i < 4; i++) {
            const uint32_t so = (uint32_t)((l_row0 + 32 * i) * 128) + s_sw;
            cp_async16(sstage + so,          Ag + (size_t)(32 * i) * KK + k0);
            cp_async16(sstage + 16384u + so, Bg + (size_t)(32 * i) * KK + k0);
        }
    };

    constexpr int S = KK >> 6;
    load_stage(0,  sbase);               cp_commit();
    load_stage(64, sbase + STAGE_BYTES); cp_commit();

    uint32_t s_cur  = sbase;
    uint32_t s_next = sbase + 2 * STAGE_BYTES;
    #pragma unroll 1
    for (int s = 0; s < S; s++) {
        cp_wait1();
        __syncthreads();

        if (s + 2 < S) load_stage((s + 2) << 6, s_next);
        cp_commit();
        s_next += STAGE_BYTES;
        if (s_next == sbase + 3 * STAGE_BYTES) s_next = sbase;

        #pragma unroll
        for (int ks = 0; ks < 4; ks++) {
            const uint32_t kx = (uint32_t)(ks * 32);
            uint32_t a[2][4];
            #pragma unroll
            for (int mt = 0; mt < 2; mt++)
                ldsm_x4(a[mt], (s_cur + Ra[mt]) ^ kx);
            uint32_t bfr[4][4];
            #pragma unroll
            for (int bt = 0; bt < 4; bt++)
                ldsm_x4(bfr[bt], (s_cur + Rb[bt]) ^ kx);
            #pragma unroll
            for (int mt = 0; mt < 2; mt++)
                #pragma unroll
                for (int nt = 0; nt < 8; nt++) {
                    const int bt = nt >> 1, wh = nt & 1;
                    mma16816(acc[mt][nt], a[mt], bfr[bt][wh], bfr[bt][wh + 2]);
                }
        }
        s_cur += STAGE_BYTES;
        if (s_cur == sbase + 3 * STAGE_BYTES) s_cur = sbase;
    }

    // epilogue
    const int colq = (lane & 3) * 2;
    const int rowq = lane >> 2;
    #pragma unroll
    for (int mt = 0; mt < 2; mt++) {
        #pragma unroll
        for (int nt = 0; nt < 8; nt++) {
            const int col = bn + wn * 64 + nt * 8 + colq;
            const float2 bz = *(const float2*)(bias + col);
            #pragma unroll
            for (int hh = 0; hh < 2; hh++) {
                const int grow = bm + wm * 32 + mt * 16 + rowq + hh * 8;
                float2 v;
                v.x = acc[mt][nt][hh * 2 + 0] + bz.x;
                v.y = acc[mt][nt][hh * 2 + 1] + bz.y;
                if (EPI == EPI_RES) {
                    const float2 r = *(const float2*)(res + (size_t)grow * N + col);
                    v.x += r.x; v.y += r.y;
                }
                if (EPI == EPI_GELU) {
                    v.x = gelu_exact(v.x); v.y = gelu_exact(v.y);
                }
                if (H_OUT) {
                    *(uint32_t*)(Ch + (size_t)grow * N + col) = pack_h2(v.x, v.y);
                } else {
                    *(float2*)(C + (size_t)grow * N + col) = v;
                }
            }
        }
    }
}

// ---------------------------------------------------------------------------
// Launch
// ---------------------------------------------------------------------------
extern "C" void kernel_launch(void* const* d_in, const int* in_sizes, int n_in,
                              void* d_out, int out_size)
{
    const float* x      = (const float*)d_in[0];
    const float* qkv_w  = (const float*)d_in[1];
    const float* qkv_b  = (const float*)d_in[2];
    const float* proj_w = (const float*)d_in[3];
    const float* proj_b = (const float*)d_in[4];
    const float* ln1_w  = (const float*)d_in[5];
    const float* ln1_b  = (const float*)d_in[6];
    const float* ln2_w  = (const float*)d_in[7];
    const float* ln2_b  = (const float*)d_in[8];
    const float* mlp_w1 = (const float*)d_in[9];
    const float* mlp_b1 = (const float*)d_in[10];
    const float* mlp_w2 = (const float*)d_in[11];
    const float* mlp_b2 = (const float*)d_in[12];
    float* out = (float*)d_out;

    float *x1;
    __half *qkvh, *act, *amlp, *wsq, *wsp, *ws1, *ws2;
    cudaGetSymbolAddress((void**)&x1,   g_x1);
    cudaGetSymbolAddress((void**)&qkvh, g_qkvh);
    cudaGetSymbolAddress((void**)&act,  g_act);
    cudaGetSymbolAddress((void**)&amlp, g_amlp);
    cudaGetSymbolAddress((void**)&wsq,  g_ws_qkv);
    cudaGetSymbolAddress((void**)&wsp,  g_ws_proj);
    cudaGetSymbolAddress((void**)&ws1,  g_ws_w1);
    cudaGetSymbolAddress((void**)&ws2,  g_ws_w2);

    const int SMEM = STAGES * STAGE_BYTES;   // 96KB
    cudaFuncSetAttribute((gemm_mma<EPI_BIAS, true,  3072, 1024>), cudaFuncAttributeMaxDynamicSharedMemorySize, SMEM);
    cudaFuncSetAttribute((gemm_mma<EPI_RES,  false, 1024, 1024>), cudaFuncAttributeMaxDynamicSharedMemorySize, SMEM);
    cudaFuncSetAttribute((gemm_mma<EPI_GELU, true,  4096, 1024>), cudaFuncAttributeMaxDynamicSharedMemorySize, SMEM);
    cudaFuncSetAttribute((gemm_mma<EPI_RES,  false, 1024, 4096>), cudaFuncAttributeMaxDynamicSharedMemorySize, SMEM);

    const int M = M_ROWS;

    // 0) all weight converts in one launch (12288 blocks)
    conv_all_kernel<<<12288, 256>>>(qkv_w, wsq, proj_w, wsp, mlp_w1, ws1, mlp_w2, ws2);

    // 1) act = fp16(LN1(x))
    ln_h_kernel<<<M, 256>>>(x, ln1_w, ln1_b, act);

    // 2) qkvh = fp16(act @ qkv_w^T + qkv_b)
    gemm_mma<EPI_BIAS, true, 3072, 1024><<<dim3(3072 / 128, M / 128), 256, SMEM>>>(
        act, wsq, qkv_b, nullptr, nullptr, qkvh);

    // 3) attention -> act (fp16)
    attn_h_kernel<<<M, 128>>>(qkvh, act);

    // 4) x1 = x + act @ proj_w^T + proj_b
    gemm_mma<EPI_RES, false, 1024, 1024><<<dim3(1024 / 128, M / 128), 256, SMEM>>>(
        act, wsp, proj_b, x, x1, nullptr);

    // 5) act = fp16(LN2(x1))
    ln_h_kernel<<<M, 256>>>(x1, ln2_w, ln2_b, act);

    // 6) amlp = fp16(gelu(act @ w1^T + b1))
    gemm_mma<EPI_GELU, true, 4096, 1024><<<dim3(4096 / 128, M / 128), 256, SMEM>>>(
        act, ws1, mlp_b1, nullptr, nullptr, amlp);

    // 7) out = x1 + amlp @ w2^T + b2
    gemm_mma<EPI_RES, false, 1024, 4096><<<dim3(1024 / 128, M / 128), 256, SMEM>>>(
        amlp, ws2, mlp_b2, x1, out, nullptr);
}